// round 3
// baseline (speedup 1.0000x reference)
#include <cuda_runtime.h>
#include <mma.h>
#include <math.h>
#include <stdint.h>

using namespace nvcuda;

#define D_EMB 1024
#define NB 8
#define SQ 577
#define SK 13271
#define SKP 13312      // SK padded to 128
#define ROWP 640       // SQ padded to 128
#define SQP 640        // self-attn K padded
#define LNEPS 1e-5f

// ---------------- scratch (__device__ globals) ------------------------------
__device__ float g_normX[(size_t)NB * SK * D_EMB];
__device__ float g_normQ[(size_t)NB * SQ * D_EMB];
__device__ float g_S   [(size_t)NB * ROWP * SKP];
__device__ float g_att [(size_t)NB * ROWP * D_EMB];
__device__ float g_cross[(size_t)NB * SQ * D_EMB];
__device__ float g_normC[(size_t)NB * SQ * D_EMB];
__device__ float g_S2  [(size_t)NB * ROWP * SQP];
__device__ float g_self[(size_t)NB * ROWP * D_EMB];

// ---------------- reductions (blockDim == 256) ------------------------------
__device__ __forceinline__ float block_sum(float v, float* red) {
    #pragma unroll
    for (int o = 16; o > 0; o >>= 1) v += __shfl_xor_sync(0xffffffffu, v, o);
    int w = threadIdx.x >> 5;
    if ((threadIdx.x & 31) == 0) red[w] = v;
    __syncthreads();
    float s = 0.f;
    #pragma unroll
    for (int i = 0; i < 8; i++) s += red[i];
    __syncthreads();
    return s;
}
__device__ __forceinline__ float block_max(float v, float* red) {
    #pragma unroll
    for (int o = 16; o > 0; o >>= 1) v = fmaxf(v, __shfl_xor_sync(0xffffffffu, v, o));
    int w = threadIdx.x >> 5;
    if ((threadIdx.x & 31) == 0) red[w] = v;
    __syncthreads();
    float s = -INFINITY;
    #pragma unroll
    for (int i = 0; i < 8; i++) s = fmaxf(s, red[i]);
    __syncthreads();
    return s;
}

// ---------------- layernorm (tf32-truncated output) -------------------------
__global__ void ln_kernel(const float* __restrict__ in, const float* __restrict__ w,
                          const float* __restrict__ b, float* __restrict__ out) {
    __shared__ float red[8];
    size_t row = blockIdx.x;
    float4 v = ((const float4*)(in + row * D_EMB))[threadIdx.x];
    float mean = block_sum(v.x + v.y + v.z + v.w, red) * (1.f / D_EMB);
    float dx = v.x - mean, dy = v.y - mean, dz = v.z - mean, dw = v.w - mean;
    float var = block_sum(dx*dx + dy*dy + dz*dz + dw*dw, red) * (1.f / D_EMB);
    float inv = rsqrtf(var + LNEPS);
    float4 w4 = ((const float4*)w)[threadIdx.x];
    float4 b4 = ((const float4*)b)[threadIdx.x];
    float4 o;
    o.x = wmma::__float_to_tf32(dx * inv * w4.x + b4.x);
    o.y = wmma::__float_to_tf32(dy * inv * w4.y + b4.y);
    o.z = wmma::__float_to_tf32(dz * inv * w4.z + b4.z);
    o.w = wmma::__float_to_tf32(dw * inv * w4.w + b4.w);
    ((float4*)(out + row * D_EMB))[threadIdx.x] = o;
}

// ---------------- softmax: row cached in smem, pads zeroed ------------------
__global__ void softmax_kernel(float* __restrict__ S, int n, int np, int sq, int rowp) {
    extern __shared__ float buf[];
    __shared__ float red[8];
    int b = blockIdx.x / sq, r = blockIdx.x % sq;
    float* p = S + ((size_t)b * rowp + r) * np;
    float m = -INFINITY;
    for (int i = threadIdx.x; i < n; i += 256) { float v = p[i]; buf[i] = v; m = fmaxf(m, v); }
    m = block_max(m, red);
    float s = 0.f;
    for (int i = threadIdx.x; i < n; i += 256) { float e = __expf(buf[i] - m); buf[i] = e; s += e; }
    s = block_sum(s, red);
    float inv = 1.f / s;
    for (int i = threadIdx.x; i < n; i += 256) p[i] = wmma::__float_to_tf32(buf[i] * inv);
    for (int i = n + threadIdx.x; i < np; i += 256) p[i] = 0.f;
}

// ---------------- cp.async helper -------------------------------------------
__device__ __forceinline__ void cp16(float* dst, const float* src, bool pred) {
    uint32_t d = (uint32_t)__cvta_generic_to_shared(dst);
    int sz = pred ? 16 : 0;
    asm volatile("cp.async.cg.shared.global [%0], [%1], 16, %2;\n" :: "r"(d), "l"(src), "r"(sz));
}

// ---------------- tf32 wmma GEMM, 64x64 warp tiles, 3-stage pipeline --------
// Block tile (WGM*64) x (WGN*64), BK=32, threads = WGM*WGN*32.
// C[m][n] = alpha * sum_k A[m][k] * Bop[k][n]
// TRANS_B=true : B is [N,K] row-major.  TRANS_B=false: B is [K,N] row-major.
// C fully padded (direct stores). A row stride == K. M/N/K edges zfilled.
template <int WGM, int WGN, bool TRANS_B>
__global__ __launch_bounds__(WGM * WGN * 32)
void gemm_tf32(const float* __restrict__ A, const float* __restrict__ B, float* __restrict__ C,
               int Mreal, int Nreal, int K, int Kreal, int ldb_n, int ldc,
               size_t sA, size_t sB, size_t sC, float alpha) {
    constexpr int BM = WGM * 64, BN = WGN * 64;
    constexpr int T = WGM * WGN * 32;
    constexpr int ASZ = BM * 36;
    constexpr int BLDN = BN + 4;
    constexpr int BSZ = TRANS_B ? BN * 36 : 32 * BLDN;
    constexpr int STAGE = ASZ + BSZ;

    extern __shared__ float sm[];

    A += blockIdx.z * sA;  B += blockIdx.z * sB;  C += blockIdx.z * sC;
    const int m0 = blockIdx.y * BM, n0 = blockIdx.x * BN;
    const int tid = threadIdx.x, warp = tid >> 5;
    const int wm = warp / WGN, wn = warp % WGN;

    wmma::fragment<wmma::accumulator, 16, 16, 8, float> acc[4][4];
    #pragma unroll
    for (int i = 0; i < 4; i++)
        #pragma unroll
        for (int j = 0; j < 4; j++) wmma::fill_fragment(acc[i][j], 0.f);

    auto load_tile = [&](int kt, int bufi) {
        const int k0 = kt * 32;
        float* as = sm + bufi * STAGE;
        float* bs = as + ASZ;
        #pragma unroll
        for (int i = 0; i < (BM * 8) / T; i++) {
            int idx = tid + i * T;
            int r = idx >> 3, v = (idx & 7) * 4;
            int gr = m0 + r;
            cp16(as + r * 36 + v, A + (size_t)gr * K + k0 + v, gr < Mreal);
        }
        if (TRANS_B) {
            #pragma unroll
            for (int i = 0; i < (BN * 8) / T; i++) {
                int idx = tid + i * T;
                int r = idx >> 3, v = (idx & 7) * 4;
                int gn = n0 + r;
                cp16(bs + r * 36 + v, B + (size_t)gn * K + k0 + v, gn < Nreal);
            }
        } else {
            #pragma unroll
            for (int i = 0; i < (8 * BN) / T; i++) {
                int idx = tid + i * T;
                int kk = idx / (BN / 4), v = (idx % (BN / 4)) * 4;
                int gk = k0 + kk;
                cp16(bs + kk * BLDN + v, B + (size_t)gk * ldb_n + n0 + v, gk < Kreal);
            }
        }
        asm volatile("cp.async.commit_group;\n");
    };

    const int KT = K / 32;
    load_tile(0, 0);
    load_tile(1, 1);

    for (int kt = 0; kt < KT; kt++) {
        if (kt + 1 < KT) asm volatile("cp.async.wait_group 1;\n");
        else             asm volatile("cp.async.wait_group 0;\n");
        __syncthreads();
        if (kt + 2 < KT) load_tile(kt + 2, (kt + 2) % 3);

        const int bufi = kt % 3;
        float* as = sm + bufi * STAGE;
        float* bs = as + ASZ;
        #pragma unroll
        for (int ks = 0; ks < 4; ks++) {
            wmma::fragment<wmma::matrix_a, 16, 16, 8, wmma::precision::tf32, wmma::row_major> af[4];
            #pragma unroll
            for (int i = 0; i < 4; i++)
                wmma::load_matrix_sync(af[i], as + (wm * 64 + i * 16) * 36 + ks * 8, 36);
            if (TRANS_B) {
                #pragma unroll
                for (int j = 0; j < 4; j++) {
                    wmma::fragment<wmma::matrix_b, 16, 16, 8, wmma::precision::tf32, wmma::col_major> bf;
                    wmma::load_matrix_sync(bf, bs + (wn * 64 + j * 16) * 36 + ks * 8, 36);
                    #pragma unroll
                    for (int i = 0; i < 4; i++) wmma::mma_sync(acc[i][j], af[i], bf, acc[i][j]);
                }
            } else {
                #pragma unroll
                for (int j = 0; j < 4; j++) {
                    wmma::fragment<wmma::matrix_b, 16, 16, 8, wmma::precision::tf32, wmma::row_major> bf;
                    wmma::load_matrix_sync(bf, bs + ks * 8 * BLDN + wn * 64 + j * 16, BLDN);
                    #pragma unroll
                    for (int i = 0; i < 4; i++) wmma::mma_sync(acc[i][j], af[i], bf, acc[i][j]);
                }
            }
        }
        __syncthreads();
    }

    #pragma unroll
    for (int i = 0; i < 4; i++)
        #pragma unroll
        for (int j = 0; j < 4; j++) {
            #pragma unroll
            for (int e = 0; e < 8; e++) acc[i][j].x[e] *= alpha;
            int rg = m0 + wm * 64 + i * 16, cg = n0 + wn * 64 + j * 16;
            wmma::store_matrix_sync(C + (size_t)rg * ldc + cg, acc[i][j], ldc, wmma::mem_row_major);
        }
}

// ---------------- fused MLP (D->4->D, exact-erf GELU) -----------------------
__global__ void mlp_kernel(const float* __restrict__ att, const float* __restrict__ w1,
                           const float* __restrict__ b1, const float* __restrict__ w2,
                           const float* __restrict__ b2, float* __restrict__ out) {
    __shared__ float red[4][8];
    __shared__ float hh[4];
    int b = blockIdx.x / SQ, r = blockIdx.x % SQ;
    float4 v = ((const float4*)(att + ((size_t)b * ROWP + r) * D_EMB))[threadIdx.x];
    #pragma unroll
    for (int h = 0; h < 4; h++) {
        float4 w = ((const float4*)(w1 + (size_t)h * D_EMB))[threadIdx.x];
        float p = v.x * w.x + v.y * w.y + v.z * w.z + v.w * w.w;
        #pragma unroll
        for (int o = 16; o > 0; o >>= 1) p += __shfl_xor_sync(0xffffffffu, p, o);
        if ((threadIdx.x & 31) == 0) red[h][threadIdx.x >> 5] = p;
    }
    __syncthreads();
    if (threadIdx.x < 4) {
        float s = b1[threadIdx.x];
        #pragma unroll
        for (int i = 0; i < 8; i++) s += red[threadIdx.x][i];
        hh[threadIdx.x] = 0.5f * s * (1.f + erff(s * 0.70710678118654752f));
    }
    __syncthreads();
    float h0 = hh[0], h1 = hh[1], h2 = hh[2], h3 = hh[3];
    int d = threadIdx.x * 4;
    float4 wa = ((const float4*)w2)[d + 0];
    float4 wb = ((const float4*)w2)[d + 1];
    float4 wc = ((const float4*)w2)[d + 2];
    float4 wd = ((const float4*)w2)[d + 3];
    float4 o;
    o.x = h0 * wa.x + h1 * wa.y + h2 * wa.z + h3 * wa.w + b2[d + 0];
    o.y = h0 * wb.x + h1 * wb.y + h2 * wb.z + h3 * wb.w + b2[d + 1];
    o.z = h0 * wc.x + h1 * wc.y + h2 * wc.z + h3 * wc.w + b2[d + 2];
    o.w = h0 * wd.x + h1 * wd.y + h2 * wd.z + h3 * wd.w + b2[d + 3];
    ((float4*)(out + ((size_t)b * SQ + r) * D_EMB))[threadIdx.x] = o;
}

// ---------------- final combine ---------------------------------------------
__global__ void final_kernel(const float* __restrict__ normQ, const float* __restrict__ cross,
                             const float* __restrict__ selfa, const float* __restrict__ g1,
                             const float* __restrict__ g2, float* __restrict__ out) {
    int b = blockIdx.x / SQ, r = blockIdx.x % SQ;
    size_t ci = ((size_t)b * SQ + r) * 256 + threadIdx.x;
    size_t si = ((size_t)b * ROWP + r) * 256 + threadIdx.x;
    float4 q = ((const float4*)normQ)[ci];
    float4 c = ((const float4*)cross)[ci];
    float4 s = ((const float4*)selfa)[si];
    float4 a = ((const float4*)g1)[threadIdx.x];
    float4 bb = ((const float4*)g2)[threadIdx.x];
    float4 o;
    o.x = q.x + bb.x * (c.x + a.x * s.x);
    o.y = q.y + bb.y * (c.y + a.y * s.y);
    o.z = q.z + bb.z * (c.z + a.z * s.z);
    o.w = q.w + bb.w * (c.w + a.w * s.w);
    ((float4*)out)[ci] = o;
}

// ---------------- launch ------------------------------------------------------
extern "C" void kernel_launch(void* const* d_in, const int* in_sizes, int n_in,
                              void* d_out, int out_size) {
    const float* input_features = (const float*)d_in[0];
    const float* query_feature  = (const float*)d_in[1];
    const float* n1w = (const float*)d_in[2];
    const float* n1b = (const float*)d_in[3];
    const float* n2w = (const float*)d_in[4];
    const float* n2b = (const float*)d_in[5];
    const float* n3w = (const float*)d_in[6];
    const float* n3b = (const float*)d_in[7];
    const float* g1  = (const float*)d_in[8];
    const float* g2  = (const float*)d_in[9];
    const float* fc1w = (const float*)d_in[10];
    const float* fc1b = (const float*)d_in[11];
    const float* fc2w = (const float*)d_in[12];
    const float* fc2b = (const float*)d_in[13];

    float *normX, *normQ, *S, *att, *cross, *normC, *S2, *selfa;
    cudaGetSymbolAddress((void**)&normX, g_normX);
    cudaGetSymbolAddress((void**)&normQ, g_normQ);
    cudaGetSymbolAddress((void**)&S,     g_S);
    cudaGetSymbolAddress((void**)&att,   g_att);
    cudaGetSymbolAddress((void**)&cross, g_cross);
    cudaGetSymbolAddress((void**)&normC, g_normC);
    cudaGetSymbolAddress((void**)&S2,    g_S2);
    cudaGetSymbolAddress((void**)&selfa, g_self);

    // smem: stage = (BM*36 + BSZ) floats, 3 stages
    const int SM_QK = 3 * (128 * 36 + 128 * 36) * 4;      // 110592 B  (<2,2,true>)
    const int SM_PV = 3 * (128 * 36 + 32 * 260) * 4;      // 155136 B  (<2,4,false>)
    cudaFuncSetAttribute((const void*)gemm_tf32<2, 2, true>,  cudaFuncAttributeMaxDynamicSharedMemorySize, SM_QK);
    cudaFuncSetAttribute((const void*)gemm_tf32<2, 4, false>, cudaFuncAttributeMaxDynamicSharedMemorySize, SM_PV);
    cudaFuncSetAttribute((const void*)softmax_kernel, cudaFuncAttributeMaxDynamicSharedMemorySize, SKP * 4);

    const float scale = 0.03125f;   // 1024^-0.5

    // 1) layernorms
    ln_kernel<<<NB * SK, 256>>>(input_features, n1w, n1b, normX);
    ln_kernel<<<NB * SQ, 256>>>(query_feature,  n2w, n2b, normQ);

    // 2) cross attention
    gemm_tf32<2, 2, true><<<dim3(SKP / 128, ROWP / 128, NB), 128, SM_QK>>>(
        normQ, normX, S, SQ, SK, D_EMB, D_EMB, 0, SKP,
        (size_t)SQ * D_EMB, (size_t)SK * D_EMB, (size_t)ROWP * SKP, scale);
    softmax_kernel<<<NB * SQ, 256, SKP * 4>>>(S, SK, SKP, SQ, ROWP);
    gemm_tf32<2, 4, false><<<dim3(D_EMB / 256, ROWP / 128, NB), 256, SM_PV>>>(
        S, normX, att, SQ, D_EMB, SKP, SK, D_EMB, D_EMB,
        (size_t)ROWP * SKP, (size_t)SK * D_EMB, (size_t)ROWP * D_EMB, 1.f);

    // 3) MLP
    mlp_kernel<<<NB * SQ, 256>>>(att, fc1w, fc1b, fc2w, fc2b, cross);

    // 4) LN + self attention
    ln_kernel<<<NB * SQ, 256>>>(cross, n3w, n3b, normC);
    gemm_tf32<2, 2, true><<<dim3(SQP / 128, ROWP / 128, NB), 128, SM_QK>>>(
        normC, normC, S2, SQ, SQ, D_EMB, D_EMB, 0, SQP,
        (size_t)SQ * D_EMB, (size_t)SQ * D_EMB, (size_t)ROWP * SQP, scale);
    softmax_kernel<<<NB * SQ, 256, SQP * 4>>>(S2, SQ, SQP, SQ, ROWP);
    gemm_tf32<2, 4, false><<<dim3(D_EMB / 256, ROWP / 128, NB), 256, SM_PV>>>(
        S2, normC, selfa, SQ, D_EMB, SQP, SQ, D_EMB, D_EMB,
        (size_t)ROWP * SQP, (size_t)SQ * D_EMB, (size_t)ROWP * D_EMB, 1.f);

    // 5) combine
    final_kernel<<<NB * SQ, 256>>>(normQ, cross, selfa, g1, g2, (float*)d_out);
}

// round 4
// speedup vs baseline: 3.2232x; 3.2232x over previous
#include <cuda_runtime.h>
#include <cuda_fp16.h>
#include <mma.h>
#include <math.h>
#include <stdint.h>

using namespace nvcuda;

#define D_EMB 1024
#define NB 8
#define SQ 577
#define SK 13271
#define SKP 13312      // SK padded to 128
#define ROWP 640       // SQ padded to 128
#define SQP 640        // self-attn K padded
#define LNEPS 1e-5f

// ---------------- scratch (__device__ globals) ------------------------------
__device__ __half g_normX_h[(size_t)NB * SK * D_EMB];    // LN(input) fp16
__device__ float  g_normQ  [(size_t)NB * SQ * D_EMB];    // LN(query) fp32 (final combine)
__device__ __half g_normQ_h[(size_t)NB * SQ * D_EMB];    // LN(query) fp16 (GEMM)
__device__ float  g_S      [(size_t)NB * ROWP * SKP];    // cross scores fp32, padded
__device__ __half g_P      [(size_t)NB * ROWP * SKP];    // cross probs fp16, padded
__device__ float  g_att    [(size_t)NB * ROWP * D_EMB];  // attended fp32, padded rows
__device__ float  g_cross  [(size_t)NB * SQ * D_EMB];    // MLP out fp32, compact
__device__ __half g_normC_h[(size_t)NB * SQ * D_EMB];    // LN(cross) fp16
__device__ float  g_S2     [(size_t)NB * ROWP * SQP];    // self scores fp32, padded
__device__ __half g_P2     [(size_t)NB * ROWP * SQP];    // self probs fp16, padded
__device__ float  g_self   [(size_t)NB * ROWP * D_EMB];  // self attended fp32, padded

// ---------------- reductions (blockDim == 256) ------------------------------
__device__ __forceinline__ float block_sum(float v, float* red) {
    #pragma unroll
    for (int o = 16; o > 0; o >>= 1) v += __shfl_xor_sync(0xffffffffu, v, o);
    int w = threadIdx.x >> 5;
    if ((threadIdx.x & 31) == 0) red[w] = v;
    __syncthreads();
    float s = 0.f;
    #pragma unroll
    for (int i = 0; i < 8; i++) s += red[i];
    __syncthreads();
    return s;
}
__device__ __forceinline__ float block_max(float v, float* red) {
    #pragma unroll
    for (int o = 16; o > 0; o >>= 1) v = fmaxf(v, __shfl_xor_sync(0xffffffffu, v, o));
    int w = threadIdx.x >> 5;
    if ((threadIdx.x & 31) == 0) red[w] = v;
    __syncthreads();
    float s = -INFINITY;
    #pragma unroll
    for (int i = 0; i < 8; i++) s = fmaxf(s, red[i]);
    __syncthreads();
    return s;
}

// ---------------- layernorm -> fp16 (optionally fp32 too) -------------------
__global__ void ln_kernel(const float* __restrict__ in, const float* __restrict__ w,
                          const float* __restrict__ b, __half* __restrict__ out_h,
                          float* __restrict__ out_f) {
    __shared__ float red[8];
    size_t row = blockIdx.x;
    float4 v = ((const float4*)(in + row * D_EMB))[threadIdx.x];
    float mean = block_sum(v.x + v.y + v.z + v.w, red) * (1.f / D_EMB);
    float dx = v.x - mean, dy = v.y - mean, dz = v.z - mean, dw = v.w - mean;
    float var = block_sum(dx*dx + dy*dy + dz*dz + dw*dw, red) * (1.f / D_EMB);
    float inv = rsqrtf(var + LNEPS);
    float4 w4 = ((const float4*)w)[threadIdx.x];
    float4 b4 = ((const float4*)b)[threadIdx.x];
    float ox = dx * inv * w4.x + b4.x;
    float oy = dy * inv * w4.y + b4.y;
    float oz = dz * inv * w4.z + b4.z;
    float ow = dw * inv * w4.w + b4.w;
    __half2 h0 = __floats2half2_rn(ox, oy);
    __half2 h1 = __floats2half2_rn(oz, ow);
    uint2 packed = { *(uint32_t*)&h0, *(uint32_t*)&h1 };
    ((uint2*)(out_h + row * D_EMB))[threadIdx.x] = packed;
    if (out_f) {
        float4 o = { ox, oy, oz, ow };
        ((float4*)(out_f + row * D_EMB))[threadIdx.x] = o;
    }
}

// ---------------- softmax: fp32 scores in -> fp16 probs out -----------------
__global__ void softmax_kernel(const float* __restrict__ S, __half* __restrict__ P,
                               int n, int np, int sq, int rowp) {
    extern __shared__ float buf[];
    __shared__ float red[8];
    int b = blockIdx.x / sq, r = blockIdx.x % sq;
    const float* src = S + ((size_t)b * rowp + r) * np;
    __half* dst = P + ((size_t)b * rowp + r) * np;
    float m = -INFINITY;
    for (int i = threadIdx.x; i < n; i += 256) { float v = src[i]; buf[i] = v; m = fmaxf(m, v); }
    m = block_max(m, red);
    float s = 0.f;
    for (int i = threadIdx.x; i < n; i += 256) { float e = __expf(buf[i] - m); buf[i] = e; s += e; }
    s = block_sum(s, red);
    float inv = 1.f / s;
    for (int i = threadIdx.x; i < n; i += 256) dst[i] = __float2half_rn(buf[i] * inv);
    for (int i = n + threadIdx.x; i < np; i += 256) dst[i] = __ushort_as_half(0);
}

// ---------------- cp.async helper -------------------------------------------
__device__ __forceinline__ void cp16(void* dst, const void* src, bool pred) {
    uint32_t d = (uint32_t)__cvta_generic_to_shared(dst);
    int sz = pred ? 16 : 0;
    asm volatile("cp.async.cg.shared.global [%0], [%1], 16, %2;\n" :: "r"(d), "l"(src), "r"(sz));
}

// ---------------- fp16 wmma GEMM, BM=128, 3-stage cp.async pipeline ---------
// C[m][n] = alpha * sum_k A[m][k] * Bop[k][n], A/B fp16, C fp32 (padded, direct store)
// TRANS_B=true : B is [N,K] row-major.  TRANS_B=false: B is [K,N] row-major.
template <int WARPS_M, int WARPS_N, int BN, bool TRANS_B>
__global__ __launch_bounds__(WARPS_M * WARPS_N * 32)
void gemm_fp16(const __half* __restrict__ A, const __half* __restrict__ B, float* __restrict__ C,
               int Mreal, int Nreal, int K, int Kreal, int ldb_n, int ldc,
               size_t sA, size_t sB, size_t sC, float alpha) {
    constexpr int BM = 128;
    constexpr int T = WARPS_M * WARPS_N * 32;
    constexpr int WTM = BM / WARPS_M;          // warp tile m
    constexpr int WTN = BN / WARPS_N;          // warp tile n
    constexpr int FM = WTM / 16, FN = WTN / 16;
    constexpr int ALD = 40;                    // BK(32)+8 halfs
    constexpr int ASZ = BM * ALD;
    constexpr int BLDN = BN + 8;
    constexpr int BSZ = TRANS_B ? BN * ALD : 32 * BLDN;
    constexpr int STAGE = ASZ + BSZ;           // halfs

    extern __shared__ __half smh[];

    A += blockIdx.z * sA;  B += blockIdx.z * sB;  C += blockIdx.z * sC;
    const int m0 = blockIdx.y * BM, n0 = blockIdx.x * BN;
    const int tid = threadIdx.x, warp = tid >> 5;
    const int wm = warp / WARPS_N, wn = warp % WARPS_N;

    wmma::fragment<wmma::accumulator, 16, 16, 16, float> acc[FM][FN];
    #pragma unroll
    for (int i = 0; i < FM; i++)
        #pragma unroll
        for (int j = 0; j < FN; j++) wmma::fill_fragment(acc[i][j], 0.f);

    auto load_tile = [&](int kt, int bufi) {
        const int k0 = kt * 32;
        __half* as = smh + bufi * STAGE;
        __half* bs = as + ASZ;
        // A: BM rows x 32 halfs = 4 cp16 per row
        #pragma unroll
        for (int i = 0; i < (BM * 4) / T; i++) {
            int idx = tid + i * T;
            int r = idx >> 2, v = (idx & 3) * 8;
            int gr = m0 + r;
            cp16(as + r * ALD + v, A + (size_t)gr * K + k0 + v, gr < Mreal);
        }
        if (TRANS_B) {
            #pragma unroll
            for (int i = 0; i < (BN * 4) / T; i++) {
                int idx = tid + i * T;
                int r = idx >> 2, v = (idx & 3) * 8;
                int gn = n0 + r;
                cp16(bs + r * ALD + v, B + (size_t)gn * K + k0 + v, gn < Nreal);
            }
        } else {
            #pragma unroll
            for (int i = 0; i < (32 * BN / 8) / T; i++) {
                int idx = tid + i * T;
                int kk = idx / (BN / 8), v = (idx % (BN / 8)) * 8;
                int gk = k0 + kk;
                cp16(bs + kk * BLDN + v, B + (size_t)gk * ldb_n + n0 + v, gk < Kreal);
            }
        }
        asm volatile("cp.async.commit_group;\n");
    };

    const int KT = K / 32;
    load_tile(0, 0);
    load_tile(1, 1);

    for (int kt = 0; kt < KT; kt++) {
        if (kt + 1 < KT) asm volatile("cp.async.wait_group 1;\n");
        else             asm volatile("cp.async.wait_group 0;\n");
        __syncthreads();
        if (kt + 2 < KT) load_tile(kt + 2, (kt + 2) % 3);

        const int bufi = kt % 3;
        __half* as = smh + bufi * STAGE;
        __half* bs = as + ASZ;
        #pragma unroll
        for (int ks = 0; ks < 2; ks++) {
            wmma::fragment<wmma::matrix_a, 16, 16, 16, __half, wmma::row_major> af[FM];
            #pragma unroll
            for (int i = 0; i < FM; i++)
                wmma::load_matrix_sync(af[i], as + (wm * WTM + i * 16) * ALD + ks * 16, ALD);
            if (TRANS_B) {
                #pragma unroll
                for (int j = 0; j < FN; j++) {
                    wmma::fragment<wmma::matrix_b, 16, 16, 16, __half, wmma::col_major> bf;
                    wmma::load_matrix_sync(bf, bs + (wn * WTN + j * 16) * ALD + ks * 16, ALD);
                    #pragma unroll
                    for (int i = 0; i < FM; i++) wmma::mma_sync(acc[i][j], af[i], bf, acc[i][j]);
                }
            } else {
                #pragma unroll
                for (int j = 0; j < FN; j++) {
                    wmma::fragment<wmma::matrix_b, 16, 16, 16, __half, wmma::row_major> bf;
                    wmma::load_matrix_sync(bf, bs + ks * 16 * BLDN + wn * WTN + j * 16, BLDN);
                    #pragma unroll
                    for (int i = 0; i < FM; i++) wmma::mma_sync(acc[i][j], af[i], bf, acc[i][j]);
                }
            }
        }
        __syncthreads();
    }

    #pragma unroll
    for (int i = 0; i < FM; i++)
        #pragma unroll
        for (int j = 0; j < FN; j++) {
            #pragma unroll
            for (int e = 0; e < 8; e++) acc[i][j].x[e] *= alpha;
            int rg = m0 + wm * WTM + i * 16, cg = n0 + wn * WTN + j * 16;
            wmma::store_matrix_sync(C + (size_t)rg * ldc + cg, acc[i][j], ldc, wmma::mem_row_major);
        }
}

// ---------------- fused MLP (D->4->D, exact-erf GELU) -----------------------
__global__ void mlp_kernel(const float* __restrict__ att, const float* __restrict__ w1,
                           const float* __restrict__ b1, const float* __restrict__ w2,
                           const float* __restrict__ b2, float* __restrict__ out) {
    __shared__ float red[4][8];
    __shared__ float hh[4];
    int b = blockIdx.x / SQ, r = blockIdx.x % SQ;
    float4 v = ((const float4*)(att + ((size_t)b * ROWP + r) * D_EMB))[threadIdx.x];
    #pragma unroll
    for (int h = 0; h < 4; h++) {
        float4 w = ((const float4*)(w1 + (size_t)h * D_EMB))[threadIdx.x];
        float p = v.x * w.x + v.y * w.y + v.z * w.z + v.w * w.w;
        #pragma unroll
        for (int o = 16; o > 0; o >>= 1) p += __shfl_xor_sync(0xffffffffu, p, o);
        if ((threadIdx.x & 31) == 0) red[h][threadIdx.x >> 5] = p;
    }
    __syncthreads();
    if (threadIdx.x < 4) {
        float s = b1[threadIdx.x];
        #pragma unroll
        for (int i = 0; i < 8; i++) s += red[threadIdx.x][i];
        hh[threadIdx.x] = 0.5f * s * (1.f + erff(s * 0.70710678118654752f));
    }
    __syncthreads();
    float h0 = hh[0], h1 = hh[1], h2 = hh[2], h3 = hh[3];
    int d = threadIdx.x * 4;
    float4 wa = ((const float4*)w2)[d + 0];
    float4 wb = ((const float4*)w2)[d + 1];
    float4 wc = ((const float4*)w2)[d + 2];
    float4 wd = ((const float4*)w2)[d + 3];
    float4 o;
    o.x = h0 * wa.x + h1 * wa.y + h2 * wa.z + h3 * wa.w + b2[d + 0];
    o.y = h0 * wb.x + h1 * wb.y + h2 * wb.z + h3 * wb.w + b2[d + 1];
    o.z = h0 * wc.x + h1 * wc.y + h2 * wc.z + h3 * wc.w + b2[d + 2];
    o.w = h0 * wd.x + h1 * wd.y + h2 * wd.z + h3 * wd.w + b2[d + 3];
    ((float4*)(out + ((size_t)b * SQ + r) * D_EMB))[threadIdx.x] = o;
}

// ---------------- final combine ---------------------------------------------
__global__ void final_kernel(const float* __restrict__ normQ, const float* __restrict__ cross,
                             const float* __restrict__ selfa, const float* __restrict__ g1,
                             const float* __restrict__ g2, float* __restrict__ out) {
    int b = blockIdx.x / SQ, r = blockIdx.x % SQ;
    size_t ci = ((size_t)b * SQ + r) * 256 + threadIdx.x;
    size_t si = ((size_t)b * ROWP + r) * 256 + threadIdx.x;
    float4 q = ((const float4*)normQ)[ci];
    float4 c = ((const float4*)cross)[ci];
    float4 s = ((const float4*)selfa)[si];
    float4 a = ((const float4*)g1)[threadIdx.x];
    float4 bb = ((const float4*)g2)[threadIdx.x];
    float4 o;
    o.x = q.x + bb.x * (c.x + a.x * s.x);
    o.y = q.y + bb.y * (c.y + a.y * s.y);
    o.z = q.z + bb.z * (c.z + a.z * s.z);
    o.w = q.w + bb.w * (c.w + a.w * s.w);
    ((float4*)out)[ci] = o;
}

// ---------------- launch ------------------------------------------------------
extern "C" void kernel_launch(void* const* d_in, const int* in_sizes, int n_in,
                              void* d_out, int out_size) {
    const float* input_features = (const float*)d_in[0];
    const float* query_feature  = (const float*)d_in[1];
    const float* n1w = (const float*)d_in[2];
    const float* n1b = (const float*)d_in[3];
    const float* n2w = (const float*)d_in[4];
    const float* n2b = (const float*)d_in[5];
    const float* n3w = (const float*)d_in[6];
    const float* n3b = (const float*)d_in[7];
    const float* g1  = (const float*)d_in[8];
    const float* g2  = (const float*)d_in[9];
    const float* fc1w = (const float*)d_in[10];
    const float* fc1b = (const float*)d_in[11];
    const float* fc2w = (const float*)d_in[12];
    const float* fc2b = (const float*)d_in[13];

    __half *normX_h, *normQ_h, *normC_h, *P, *P2;
    float *normQ, *S, *att, *cross, *S2, *selfa;
    cudaGetSymbolAddress((void**)&normX_h, g_normX_h);
    cudaGetSymbolAddress((void**)&normQ,   g_normQ);
    cudaGetSymbolAddress((void**)&normQ_h, g_normQ_h);
    cudaGetSymbolAddress((void**)&S,       g_S);
    cudaGetSymbolAddress((void**)&P,       g_P);
    cudaGetSymbolAddress((void**)&att,     g_att);
    cudaGetSymbolAddress((void**)&cross,   g_cross);
    cudaGetSymbolAddress((void**)&normC_h, g_normC_h);
    cudaGetSymbolAddress((void**)&S2,      g_S2);
    cudaGetSymbolAddress((void**)&P2,      g_P2);
    cudaGetSymbolAddress((void**)&selfa,   g_self);

    // smem (bytes): QK <4,2,128,true>: 3*(128*40 + 128*40)*2 = 61440
    //               PV <2,4,256,false>: 3*(128*40 + 32*264)*2 = 81408
    const int SM_QK = 3 * (128 * 40 + 128 * 40) * 2;
    const int SM_PV = 3 * (128 * 40 + 32 * 264) * 2;
    cudaFuncSetAttribute((const void*)gemm_fp16<4, 2, 128, true>,  cudaFuncAttributeMaxDynamicSharedMemorySize, SM_QK);
    cudaFuncSetAttribute((const void*)gemm_fp16<2, 4, 256, false>, cudaFuncAttributeMaxDynamicSharedMemorySize, SM_PV);
    cudaFuncSetAttribute((const void*)softmax_kernel, cudaFuncAttributeMaxDynamicSharedMemorySize, SKP * 4);

    const float scale = 0.03125f;   // 1024^-0.5

    // 1) layernorms
    ln_kernel<<<NB * SK, 256>>>(input_features, n1w, n1b, normX_h, nullptr);
    ln_kernel<<<NB * SQ, 256>>>(query_feature,  n2w, n2b, normQ_h, normQ);

    // 2) cross attention
    gemm_fp16<4, 2, 128, true><<<dim3(SKP / 128, ROWP / 128, NB), 256, SM_QK>>>(
        normQ_h, normX_h, S, SQ, SK, D_EMB, D_EMB, 0, SKP,
        (size_t)SQ * D_EMB, (size_t)SK * D_EMB, (size_t)ROWP * SKP, scale);
    softmax_kernel<<<NB * SQ, 256, SKP * 4>>>(S, P, SK, SKP, SQ, ROWP);
    gemm_fp16<2, 4, 256, false><<<dim3(D_EMB / 256, ROWP / 128, NB), 256, SM_PV>>>(
        P, normX_h, att, SQ, D_EMB, SKP, SK, D_EMB, D_EMB,
        (size_t)ROWP * SKP, (size_t)SK * D_EMB, (size_t)ROWP * D_EMB, 1.f);

    // 3) MLP
    mlp_kernel<<<NB * SQ, 256>>>(att, fc1w, fc1b, fc2w, fc2b, cross);

    // 4) LN + self attention
    ln_kernel<<<NB * SQ, 256>>>(cross, n3w, n3b, normC_h, nullptr);
    gemm_fp16<4, 2, 128, true><<<dim3(SQP / 128, ROWP / 128, NB), 256, SM_QK>>>(
        normC_h, normC_h, S2, SQ, SQ, D_EMB, D_EMB, 0, SQP,
        (size_t)SQ * D_EMB, (size_t)SQ * D_EMB, (size_t)ROWP * SQP, scale);
    softmax_kernel<<<NB * SQ, 256, SQP * 4>>>(S2, P2, SQ, SQP, SQ, ROWP);
    gemm_fp16<2, 4, 256, false><<<dim3(D_EMB / 256, ROWP / 128, NB), 256, SM_PV>>>(
        P2, normC_h, selfa, SQ, D_EMB, SQP, SQ, D_EMB, D_EMB,
        (size_t)ROWP * SQP, (size_t)SQ * D_EMB, (size_t)ROWP * D_EMB, 1.f);

    // 5) combine
    final_kernel<<<NB * SQ, 256>>>(normQ, cross, selfa, g1, g2, (float*)d_out);
}

// round 5
// speedup vs baseline: 3.2732x; 1.0155x over previous
#include <cuda_runtime.h>
#include <cuda_fp16.h>
#include <mma.h>
#include <math.h>
#include <stdint.h>

using namespace nvcuda;

#define D_EMB 1024
#define NB 8
#define SQ 577
#define SK 13271
#define SKP 13312      // SK padded to 128
#define ROWP 640       // SQ padded to 128
#define SQP 640        // self-attn K padded
#define LNEPS 1e-5f

// ---------------- scratch (__device__ globals) ------------------------------
__device__ __half g_normX_h[(size_t)NB * SK * D_EMB];
__device__ float  g_normQ  [(size_t)NB * SQ * D_EMB];
__device__ __half g_normQ_h[(size_t)NB * SQ * D_EMB];
__device__ float  g_S      [(size_t)NB * ROWP * SKP];
__device__ __half g_P      [(size_t)NB * ROWP * SKP];
__device__ float  g_att    [(size_t)NB * ROWP * D_EMB];
__device__ float  g_cross  [(size_t)NB * SQ * D_EMB];
__device__ __half g_normC_h[(size_t)NB * SQ * D_EMB];
__device__ float  g_S2     [(size_t)NB * ROWP * SQP];
__device__ __half g_P2     [(size_t)NB * ROWP * SQP];
__device__ float  g_self   [(size_t)NB * ROWP * D_EMB];

// ---------------- reductions (blockDim == 256) ------------------------------
__device__ __forceinline__ float block_sum(float v, float* red) {
    #pragma unroll
    for (int o = 16; o > 0; o >>= 1) v += __shfl_xor_sync(0xffffffffu, v, o);
    int w = threadIdx.x >> 5;
    if ((threadIdx.x & 31) == 0) red[w] = v;
    __syncthreads();
    float s = 0.f;
    #pragma unroll
    for (int i = 0; i < 8; i++) s += red[i];
    __syncthreads();
    return s;
}
__device__ __forceinline__ float block_max(float v, float* red) {
    #pragma unroll
    for (int o = 16; o > 0; o >>= 1) v = fmaxf(v, __shfl_xor_sync(0xffffffffu, v, o));
    int w = threadIdx.x >> 5;
    if ((threadIdx.x & 31) == 0) red[w] = v;
    __syncthreads();
    float s = -INFINITY;
    #pragma unroll
    for (int i = 0; i < 8; i++) s = fmaxf(s, red[i]);
    __syncthreads();
    return s;
}

// ---------------- layernorm -> fp16 (optionally fp32 too) -------------------
__global__ void ln_kernel(const float* __restrict__ in, const float* __restrict__ w,
                          const float* __restrict__ b, __half* __restrict__ out_h,
                          float* __restrict__ out_f) {
    __shared__ float red[8];
    size_t row = blockIdx.x;
    float4 v = ((const float4*)(in + row * D_EMB))[threadIdx.x];
    float mean = block_sum(v.x + v.y + v.z + v.w, red) * (1.f / D_EMB);
    float dx = v.x - mean, dy = v.y - mean, dz = v.z - mean, dw = v.w - mean;
    float var = block_sum(dx*dx + dy*dy + dz*dz + dw*dw, red) * (1.f / D_EMB);
    float inv = rsqrtf(var + LNEPS);
    float4 w4 = ((const float4*)w)[threadIdx.x];
    float4 b4 = ((const float4*)b)[threadIdx.x];
    float ox = dx * inv * w4.x + b4.x;
    float oy = dy * inv * w4.y + b4.y;
    float oz = dz * inv * w4.z + b4.z;
    float ow = dw * inv * w4.w + b4.w;
    __half2 h0 = __floats2half2_rn(ox, oy);
    __half2 h1 = __floats2half2_rn(oz, ow);
    uint2 packed = { *(uint32_t*)&h0, *(uint32_t*)&h1 };
    ((uint2*)(out_h + row * D_EMB))[threadIdx.x] = packed;
    if (out_f) {
        float4 o = { ox, oy, oz, ow };
        ((float4*)(out_f + row * D_EMB))[threadIdx.x] = o;
    }
}

// ---------------- softmax: fp32 scores in -> fp16 probs out -----------------
__global__ void softmax_kernel(const float* __restrict__ S, __half* __restrict__ P,
                               int n, int np, int sq, int rowp) {
    extern __shared__ float buf[];
    __shared__ float red[8];
    int b = blockIdx.x / sq, r = blockIdx.x % sq;
    const float* src = S + ((size_t)b * rowp + r) * np;
    __half* dst = P + ((size_t)b * rowp + r) * np;
    float m = -INFINITY;
    for (int i = threadIdx.x; i < n; i += 256) { float v = src[i]; buf[i] = v; m = fmaxf(m, v); }
    m = block_max(m, red);
    float s = 0.f;
    for (int i = threadIdx.x; i < n; i += 256) { float e = __expf(buf[i] - m); buf[i] = e; s += e; }
    s = block_sum(s, red);
    float inv = 1.f / s;
    for (int i = threadIdx.x; i < n; i += 256) dst[i] = __float2half_rn(buf[i] * inv);
    for (int i = n + threadIdx.x; i < np; i += 256) dst[i] = __ushort_as_half(0);
}

// ---------------- cp.async helper -------------------------------------------
__device__ __forceinline__ void cp16(void* dst, const void* src, bool pred) {
    uint32_t d = (uint32_t)__cvta_generic_to_shared(dst);
    int sz = pred ? 16 : 0;
    asm volatile("cp.async.cg.shared.global [%0], [%1], 16, %2;\n" :: "r"(d), "l"(src), "r"(sz));
}

// ---------------- fp16 wmma GEMM, BM=128, 4-stage, 1 sync per k-tile --------
// C[m][n] = alpha * sum_k A[m][k] * Bop[k][n], A/B fp16, C fp32 (padded, direct store)
// TRANS_B=true : B is [N,K] row-major.  TRANS_B=false: B is [K,N] row-major.
template <int WARPS_M, int WARPS_N, int BN, bool TRANS_B>
__global__ __launch_bounds__(WARPS_M * WARPS_N * 32)
void gemm_fp16(const __half* __restrict__ A, const __half* __restrict__ B, float* __restrict__ C,
               int Mreal, int Nreal, int K, int Kreal, int ldb_n, int ldc,
               size_t sA, size_t sB, size_t sC, float alpha) {
    constexpr int BM = 128;
    constexpr int T = WARPS_M * WARPS_N * 32;
    constexpr int WTM = BM / WARPS_M;
    constexpr int WTN = BN / WARPS_N;
    constexpr int FM = WTM / 16, FN = WTN / 16;
    constexpr int ALD = 40;                    // 32+8 halfs
    constexpr int ASZ = BM * ALD;
    constexpr int BLDN = BN + 8;
    constexpr int BSZ = TRANS_B ? BN * ALD : 32 * BLDN;
    constexpr int STAGE = ASZ + BSZ;           // halfs
    constexpr int NS = 4;                      // pipeline stages

    extern __shared__ __half smh[];

    A += blockIdx.z * sA;  B += blockIdx.z * sB;  C += blockIdx.z * sC;
    const int m0 = blockIdx.y * BM, n0 = blockIdx.x * BN;
    const int tid = threadIdx.x, warp = tid >> 5;
    const int wm = warp / WARPS_N, wn = warp % WARPS_N;

    wmma::fragment<wmma::accumulator, 16, 16, 16, float> acc[FM][FN];
    #pragma unroll
    for (int i = 0; i < FM; i++)
        #pragma unroll
        for (int j = 0; j < FN; j++) wmma::fill_fragment(acc[i][j], 0.f);

    auto load_tile = [&](int kt, int bufi) {
        const int k0 = kt * 32;
        __half* as = smh + bufi * STAGE;
        __half* bs = as + ASZ;
        #pragma unroll
        for (int i = 0; i < (BM * 4) / T; i++) {
            int idx = tid + i * T;
            int r = idx >> 2, v = (idx & 3) * 8;
            int gr = m0 + r;
            cp16(as + r * ALD + v, A + (size_t)gr * K + k0 + v, gr < Mreal);
        }
        if (TRANS_B) {
            #pragma unroll
            for (int i = 0; i < (BN * 4) / T; i++) {
                int idx = tid + i * T;
                int r = idx >> 2, v = (idx & 3) * 8;
                int gn = n0 + r;
                cp16(bs + r * ALD + v, B + (size_t)gn * K + k0 + v, gn < Nreal);
            }
        } else {
            #pragma unroll
            for (int i = 0; i < (32 * BN / 8) / T; i++) {
                int idx = tid + i * T;
                int kk = idx / (BN / 8), v = (idx % (BN / 8)) * 8;
                int gk = k0 + kk;
                cp16(bs + kk * BLDN + v, B + (size_t)gk * ldb_n + n0 + v, gk < Kreal);
            }
        }
        asm volatile("cp.async.commit_group;\n");
    };

    const int KT = K / 32;
    load_tile(0, 0);
    load_tile(1, 1);
    load_tile(2, 2);

    for (int kt = 0; kt < KT; kt++) {
        const int pend = KT - kt - 1;          // groups allowed to stay in flight
        if (pend >= 2)      asm volatile("cp.async.wait_group 2;\n");
        else if (pend == 1) asm volatile("cp.async.wait_group 1;\n");
        else                asm volatile("cp.async.wait_group 0;\n");
        __syncthreads();   // data for kt visible; all warps done with buf (kt-1)%NS
        if (kt + 3 < KT) load_tile(kt + 3, (kt + 3) % NS);

        const int bufi = kt % NS;
        __half* as = smh + bufi * STAGE;
        __half* bs = as + ASZ;
        #pragma unroll
        for (int ks = 0; ks < 2; ks++) {
            wmma::fragment<wmma::matrix_a, 16, 16, 16, __half, wmma::row_major> af[FM];
            #pragma unroll
            for (int i = 0; i < FM; i++)
                wmma::load_matrix_sync(af[i], as + (wm * WTM + i * 16) * ALD + ks * 16, ALD);
            if (TRANS_B) {
                #pragma unroll
                for (int j = 0; j < FN; j++) {
                    wmma::fragment<wmma::matrix_b, 16, 16, 16, __half, wmma::col_major> bf;
                    wmma::load_matrix_sync(bf, bs + (wn * WTN + j * 16) * ALD + ks * 16, ALD);
                    #pragma unroll
                    for (int i = 0; i < FM; i++) wmma::mma_sync(acc[i][j], af[i], bf, acc[i][j]);
                }
            } else {
                #pragma unroll
                for (int j = 0; j < FN; j++) {
                    wmma::fragment<wmma::matrix_b, 16, 16, 16, __half, wmma::row_major> bf;
                    wmma::load_matrix_sync(bf, bs + ks * 16 * BLDN + wn * WTN + j * 16, BLDN);
                    #pragma unroll
                    for (int i = 0; i < FM; i++) wmma::mma_sync(acc[i][j], af[i], bf, acc[i][j]);
                }
            }
        }
        // no trailing sync: the top barrier of iteration kt+1 provides the
        // cross-warp ordering before buffer (kt+3)%NS is overwritten.
    }

    #pragma unroll
    for (int i = 0; i < FM; i++)
        #pragma unroll
        for (int j = 0; j < FN; j++) {
            #pragma unroll
            for (int e = 0; e < 8; e++) acc[i][j].x[e] *= alpha;
            int rg = m0 + wm * WTM + i * 16, cg = n0 + wn * WTN + j * 16;
            wmma::store_matrix_sync(C + (size_t)rg * ldc + cg, acc[i][j], ldc, wmma::mem_row_major);
        }
}

// ---------------- fused MLP (D->4->D, exact-erf GELU) -----------------------
__global__ void mlp_kernel(const float* __restrict__ att, const float* __restrict__ w1,
                           const float* __restrict__ b1, const float* __restrict__ w2,
                           const float* __restrict__ b2, float* __restrict__ out) {
    __shared__ float red[4][8];
    __shared__ float hh[4];
    int b = blockIdx.x / SQ, r = blockIdx.x % SQ;
    float4 v = ((const float4*)(att + ((size_t)b * ROWP + r) * D_EMB))[threadIdx.x];
    #pragma unroll
    for (int h = 0; h < 4; h++) {
        float4 w = ((const float4*)(w1 + (size_t)h * D_EMB))[threadIdx.x];
        float p = v.x * w.x + v.y * w.y + v.z * w.z + v.w * w.w;
        #pragma unroll
        for (int o = 16; o > 0; o >>= 1) p += __shfl_xor_sync(0xffffffffu, p, o);
        if ((threadIdx.x & 31) == 0) red[h][threadIdx.x >> 5] = p;
    }
    __syncthreads();
    if (threadIdx.x < 4) {
        float s = b1[threadIdx.x];
        #pragma unroll
        for (int i = 0; i < 8; i++) s += red[threadIdx.x][i];
        hh[threadIdx.x] = 0.5f * s * (1.f + erff(s * 0.70710678118654752f));
    }
    __syncthreads();
    float h0 = hh[0], h1 = hh[1], h2 = hh[2], h3 = hh[3];
    int d = threadIdx.x * 4;
    float4 wa = ((const float4*)w2)[d + 0];
    float4 wb = ((const float4*)w2)[d + 1];
    float4 wc = ((const float4*)w2)[d + 2];
    float4 wd = ((const float4*)w2)[d + 3];
    float4 o;
    o.x = h0 * wa.x + h1 * wa.y + h2 * wa.z + h3 * wa.w + b2[d + 0];
    o.y = h0 * wb.x + h1 * wb.y + h2 * wb.z + h3 * wb.w + b2[d + 1];
    o.z = h0 * wc.x + h1 * wc.y + h2 * wc.z + h3 * wc.w + b2[d + 2];
    o.w = h0 * wd.x + h1 * wd.y + h2 * wd.z + h3 * wd.w + b2[d + 3];
    ((float4*)(out + ((size_t)b * SQ + r) * D_EMB))[threadIdx.x] = o;
}

// ---------------- final combine ---------------------------------------------
__global__ void final_kernel(const float* __restrict__ normQ, const float* __restrict__ cross,
                             const float* __restrict__ selfa, const float* __restrict__ g1,
                             const float* __restrict__ g2, float* __restrict__ out) {
    int b = blockIdx.x / SQ, r = blockIdx.x % SQ;
    size_t ci = ((size_t)b * SQ + r) * 256 + threadIdx.x;
    size_t si = ((size_t)b * ROWP + r) * 256 + threadIdx.x;
    float4 q = ((const float4*)normQ)[ci];
    float4 c = ((const float4*)cross)[ci];
    float4 s = ((const float4*)selfa)[si];
    float4 a = ((const float4*)g1)[threadIdx.x];
    float4 bb = ((const float4*)g2)[threadIdx.x];
    float4 o;
    o.x = q.x + bb.x * (c.x + a.x * s.x);
    o.y = q.y + bb.y * (c.y + a.y * s.y);
    o.z = q.z + bb.z * (c.z + a.z * s.z);
    o.w = q.w + bb.w * (c.w + a.w * s.w);
    ((float4*)out)[ci] = o;
}

// ---------------- launch ------------------------------------------------------
extern "C" void kernel_launch(void* const* d_in, const int* in_sizes, int n_in,
                              void* d_out, int out_size) {
    const float* input_features = (const float*)d_in[0];
    const float* query_feature  = (const float*)d_in[1];
    const float* n1w = (const float*)d_in[2];
    const float* n1b = (const float*)d_in[3];
    const float* n2w = (const float*)d_in[4];
    const float* n2b = (const float*)d_in[5];
    const float* n3w = (const float*)d_in[6];
    const float* n3b = (const float*)d_in[7];
    const float* g1  = (const float*)d_in[8];
    const float* g2  = (const float*)d_in[9];
    const float* fc1w = (const float*)d_in[10];
    const float* fc1b = (const float*)d_in[11];
    const float* fc2w = (const float*)d_in[12];
    const float* fc2b = (const float*)d_in[13];

    __half *normX_h, *normQ_h, *normC_h, *P, *P2;
    float *normQ, *S, *att, *cross, *S2, *selfa;
    cudaGetSymbolAddress((void**)&normX_h, g_normX_h);
    cudaGetSymbolAddress((void**)&normQ,   g_normQ);
    cudaGetSymbolAddress((void**)&normQ_h, g_normQ_h);
    cudaGetSymbolAddress((void**)&S,       g_S);
    cudaGetSymbolAddress((void**)&P,       g_P);
    cudaGetSymbolAddress((void**)&att,     g_att);
    cudaGetSymbolAddress((void**)&cross,   g_cross);
    cudaGetSymbolAddress((void**)&normC_h, g_normC_h);
    cudaGetSymbolAddress((void**)&S2,      g_S2);
    cudaGetSymbolAddress((void**)&P2,      g_P2);
    cudaGetSymbolAddress((void**)&selfa,   g_self);

    // smem (bytes): QK <4,2,128,true>: 4*(128*40 + 128*40)*2 = 81920
    //               PV <2,4,256,false>: 4*(128*40 + 32*264)*2 = 108544
    const int SM_QK = 4 * (128 * 40 + 128 * 40) * 2;
    const int SM_PV = 4 * (128 * 40 + 32 * 264) * 2;
    cudaFuncSetAttribute((const void*)gemm_fp16<4, 2, 128, true>,  cudaFuncAttributeMaxDynamicSharedMemorySize, SM_QK);
    cudaFuncSetAttribute((const void*)gemm_fp16<2, 4, 256, false>, cudaFuncAttributeMaxDynamicSharedMemorySize, SM_PV);
    cudaFuncSetAttribute((const void*)softmax_kernel, cudaFuncAttributeMaxDynamicSharedMemorySize, SKP * 4);

    const float scale = 0.03125f;   // 1024^-0.5

    // 1) layernorms
    ln_kernel<<<NB * SK, 256>>>(input_features, n1w, n1b, normX_h, nullptr);
    ln_kernel<<<NB * SQ, 256>>>(query_feature,  n2w, n2b, normQ_h, normQ);

    // 2) cross attention
    gemm_fp16<4, 2, 128, true><<<dim3(SKP / 128, ROWP / 128, NB), 256, SM_QK>>>(
        normQ_h, normX_h, S, SQ, SK, D_EMB, D_EMB, 0, SKP,
        (size_t)SQ * D_EMB, (size_t)SK * D_EMB, (size_t)ROWP * SKP, scale);
    softmax_kernel<<<NB * SQ, 256, SKP * 4>>>(S, P, SK, SKP, SQ, ROWP);
    gemm_fp16<2, 4, 256, false><<<dim3(D_EMB / 256, ROWP / 128, NB), 256, SM_PV>>>(
        P, normX_h, att, SQ, D_EMB, SKP, SK, D_EMB, D_EMB,
        (size_t)ROWP * SKP, (size_t)SK * D_EMB, (size_t)ROWP * D_EMB, 1.f);

    // 3) MLP
    mlp_kernel<<<NB * SQ, 256>>>(att, fc1w, fc1b, fc2w, fc2b, cross);

    // 4) LN + self attention
    ln_kernel<<<NB * SQ, 256>>>(cross, n3w, n3b, normC_h, nullptr);
    gemm_fp16<4, 2, 128, true><<<dim3(SQP / 128, ROWP / 128, NB), 256, SM_QK>>>(
        normC_h, normC_h, S2, SQ, SQ, D_EMB, D_EMB, 0, SQP,
        (size_t)SQ * D_EMB, (size_t)SQ * D_EMB, (size_t)ROWP * SQP, scale);
    softmax_kernel<<<NB * SQ, 256, SQP * 4>>>(S2, P2, SQ, SQP, SQ, ROWP);
    gemm_fp16<2, 4, 256, false><<<dim3(D_EMB / 256, ROWP / 128, NB), 256, SM_PV>>>(
        P2, normC_h, selfa, SQ, D_EMB, SQP, SQ, D_EMB, D_EMB,
        (size_t)ROWP * SQP, (size_t)SQ * D_EMB, (size_t)ROWP * D_EMB, 1.f);

    // 5) combine
    final_kernel<<<NB * SQ, 256>>>(normQ, cross, selfa, g1, g2, (float*)d_out);
}